// round 13
// baseline (speedup 1.0000x reference)
#include <cuda_runtime.h>
#include <stdint.h>

#define NUM_CLASSES 32000
#define C4  (NUM_CLASSES / 4)       // 8000 float4 slots per row
#define C8  (NUM_CLASSES / 8)       // 4000 32-byte chunks per row
#define ALPHA 0.95f
#define THREADS 512
#define NWARP (THREADS / 32)        // 16
#define P1ITER ((C8 + THREADS - 1) / THREADS)   // 8  (last iter: tid < 416)
#define P2ITER ((C4 + THREADS - 1) / THREADS)   // 16 (last iter: tid < 320)

// 256-bit load with L2::evict_last (sm_103a requires v8.b32 for this
// modifier). Pins the line in L2 until the phase-2 re-read. Not volatile:
// pure loads at distinct addresses — the compiler may hoist/batch for MLP.
__device__ __forceinline__ float ldg_el_sum32(const void* p) {
    unsigned u0, u1, u2, u3, u4, u5, u6, u7;
    asm("ld.global.L2::evict_last.v8.b32 {%0,%1,%2,%3,%4,%5,%6,%7}, [%8];"
        : "=r"(u0), "=r"(u1), "=r"(u2), "=r"(u3),
          "=r"(u4), "=r"(u5), "=r"(u6), "=r"(u7)
        : "l"(p));
    const float a = __uint_as_float(u0), b = __uint_as_float(u1);
    const float c = __uint_as_float(u2), d = __uint_as_float(u3);
    const float e = __uint_as_float(u4), f = __uint_as_float(u5);
    const float g = __uint_as_float(u6), h = __uint_as_float(u7);
    return ((a + b) + (c + d)) + ((e + f) + (g + h));
}

// Pure two-pass, L2-pinned (R1's occupancy shape + R11's cache policy):
//   - one CTA per row, 512 threads, <=32 regs -> 4 CTAs/SM, 64 warps (100%
//     theoretical occ), 4 independent barrier domains, zero staging state
//   - phase 1: whole row read as 32-B LDG.256 + L2::evict_last (pinned;
//     pinned set = 4 x 148 x 128 KB ~ 76 MB < 126 MB L2)
//   - phase 2: re-read via __ldcs (evict-first releases the line at last
//     use), scale, fused label correction, plain store
__global__ __launch_bounds__(THREADS, 4)
void distill_kernel(const float* __restrict__ x,
                    const void*  __restrict__ labels,
                    float*       __restrict__ out) {
    __shared__ float warp_sums[NWARP];

    const int row = blockIdx.x;
    const int tid = threadIdx.x;

    const float* __restrict__ xrow = x + (size_t)row * NUM_CLASSES;
    const float4* __restrict__ xr   = reinterpret_cast<const float4*>(xrow);
    float4*       __restrict__ orow = reinterpret_cast<float4*>(out + (size_t)row * NUM_CLASSES);

    // Inline label-dtype detection: probe 4 u64 words (in-bounds for both
    // int64[4096] and int32[4096] layouts). True int64 labels are all
    // < 32000; an int32 buffer viewed as u64 is < 32000 only when the
    // odd-position label is exactly 0 — P(4 in a row) ~ (1/32000)^4 ~ 1e-18.
    const unsigned long long* lu = (const unsigned long long*)labels;
    const bool is64 = (lu[0] < (unsigned long long)NUM_CLASSES) &
                      (lu[1] < (unsigned long long)NUM_CLASSES) &
                      (lu[2] < (unsigned long long)NUM_CLASSES) &
                      (lu[3] < (unsigned long long)NUM_CLASSES);

    // Label + t issued early so their latency hides under the bulk loads.
    int lab;
    if (is64) lab = (int)(((const long long*)labels)[row]);
    else      lab = ((const int*)labels)[row];
    const float t = __ldg(xrow + lab);

    // ---- Phase 1: full-row sum, 32-B loads pinned evict_last in L2 ----
    float sum = 0.0f;
    #pragma unroll
    for (int k = 0; k < P1ITER; k++) {
        const int j = tid + k * THREADS;
        if (k < P1ITER - 1 || j < C8) {
            sum += ldg_el_sum32(reinterpret_cast<const char*>(xrow) + (size_t)j * 32);
        }
    }

    // ---- Single-barrier block reduce ----
    #pragma unroll
    for (int off = 16; off > 0; off >>= 1)
        sum += __shfl_down_sync(0xffffffffu, sum, off);
    if ((tid & 31) == 0) warp_sums[tid >> 5] = sum;
    __syncthreads();
    float S = 0.0f;
    #pragma unroll
    for (int w = 0; w < NWARP; w++) S += warp_sums[w];

    const float s = ALPHA / (1.0f + S - 2.0f * t);
    const float corr = 1.0f - s * S;

    const int lab4 = lab >> 2;
    const int labc = lab & 3;

    // ---- Phase 2: re-read from pinned L2 (evict-first), scale, store ----
    #pragma unroll 8
    for (int k = 0; k < P2ITER; k++) {
        const int i = tid + k * THREADS;
        if (k < P2ITER - 1 || i < C4) {
            const float4 w = __ldcs(&xr[i]);
            float4 o;
            o.x = s * w.x;
            o.y = s * w.y;
            o.z = s * w.z;
            o.w = s * w.w;
            if (i == lab4) reinterpret_cast<float*>(&o)[labc] += corr;
            orow[i] = o;
        }
    }
}

extern "C" void kernel_launch(void* const* d_in, const int* in_sizes, int n_in,
                              void* d_out, int out_size) {
    const float* teacher_logits = (const float*)d_in[0];
    const void*  true_labels    = d_in[1];
    float* out = (float*)d_out;

    const int batch = in_sizes[1];   // 4096 rows

    distill_kernel<<<batch, THREADS>>>(teacher_logits, true_labels, out);
}

// round 14
// speedup vs baseline: 1.1508x; 1.1508x over previous
#include <cuda_runtime.h>
#include <stdint.h>

#define NUM_CLASSES 32000
#define HALF_F 16000                 // floats per CTA (half row)
#define H8 2000                      // 32-byte chunks per half
#define H4 4000                      // float4 slots per half
#define ALPHA 0.95f
#define THREADS 512
#define NWARP (THREADS / 32)         // 16
#define P1ITER 4                     // ceil(2000/512), last iter: tid < 464
#define P2ITER 8                     // ceil(4000/512), last iter: tid < 416

// 256-bit load with L2::evict_last (sm_103a needs v8.b32 for this modifier).
// Pins the line in L2 until the phase-2 re-read. Not volatile: pure loads,
// compiler may hoist/batch for MLP.
__device__ __forceinline__ float ldg_el_sum32(const void* p) {
    unsigned u0, u1, u2, u3, u4, u5, u6, u7;
    asm("ld.global.L2::evict_last.v8.b32 {%0,%1,%2,%3,%4,%5,%6,%7}, [%8];"
        : "=r"(u0), "=r"(u1), "=r"(u2), "=r"(u3),
          "=r"(u4), "=r"(u5), "=r"(u6), "=r"(u7)
        : "l"(p));
    const float a = __uint_as_float(u0), b = __uint_as_float(u1);
    const float c = __uint_as_float(u2), d = __uint_as_float(u3);
    const float e = __uint_as_float(u4), f = __uint_as_float(u5);
    const float g = __uint_as_float(u6), h = __uint_as_float(u7);
    return ((a + b) + (c + d)) + ((e + f) + (g + h));
}

__device__ __forceinline__ uint32_t smem_addr_u32(const void* p) {
    uint32_t a;
    asm("{ .reg .u64 t; cvta.to.shared.u64 t, %1; cvt.u32.u64 %0, t; }"
        : "=r"(a) : "l"(p));
    return a;
}

// 2-CTA cluster per row: each CTA owns a 64 KB half-row.
//   - pinned set = 592 CTAs x 64 KB ~ 38 MB < ~45 MB effective evict_last
//     capacity (R11/R12 vs R13 measurements) -> floor DRAM traffic
//   - 32 regs, 4 CTAs/SM -> 85% occupancy -> ~6.4 TB/s rate (R13 measurement)
//   - cross-CTA sum exchange: st.shared::cluster + one cluster barrier
//   - phase 2 reversed (hottest L2 lines re-read first)
__global__ __launch_bounds__(THREADS, 4) __cluster_dims__(2, 1, 1)
void distill_kernel(const float* __restrict__ x,
                    const void*  __restrict__ labels,
                    float*       __restrict__ out) {
    __shared__ float warp_sums[NWARP];
    __shared__ float peer_sum;               // written by the PEER CTA

    const int half = blockIdx.x & 1;         // cluster cta rank
    const int row  = blockIdx.x >> 1;
    const int tid  = threadIdx.x;

    const float* __restrict__ xrow = x + (size_t)row * NUM_CLASSES;
    const float* __restrict__ xh   = xrow + half * HALF_F;
    const float4* __restrict__ xh4 = reinterpret_cast<const float4*>(xh);
    float4* __restrict__ oh4 =
        reinterpret_cast<float4*>(out + (size_t)row * NUM_CLASSES + half * HALF_F);

    // Inline label-dtype detection: probe 4 u64 words (in-bounds for both
    // int64[4096] and int32[4096] layouts). True int64 labels are all
    // < 32000; an int32 buffer viewed as u64 is < 32000 only when the
    // odd-position label is exactly 0 — P(4 in a row) ~ (1/32000)^4 ~ 1e-18.
    const unsigned long long* lu = (const unsigned long long*)labels;
    const bool is64 = (lu[0] < (unsigned long long)NUM_CLASSES) &
                      (lu[1] < (unsigned long long)NUM_CLASSES) &
                      (lu[2] < (unsigned long long)NUM_CLASSES) &
                      (lu[3] < (unsigned long long)NUM_CLASSES);

    int lab;
    if (is64) lab = (int)(((const long long*)labels)[row]);
    else      lab = ((const int*)labels)[row];
    const float t = __ldg(xrow + lab);       // both CTAs load t (4B, L2-hot)

    // ---- Phase 1: half-row sum, 32-B loads pinned evict_last in L2 ----
    float sum = 0.0f;
    #pragma unroll
    for (int k = 0; k < P1ITER; k++) {
        const int j = tid + k * THREADS;
        if (k < P1ITER - 1 || j < H8) {
            sum += ldg_el_sum32(reinterpret_cast<const char*>(xh) + (size_t)j * 32);
        }
    }

    // ---- Block reduce (single barrier) ----
    #pragma unroll
    for (int off = 16; off > 0; off >>= 1)
        sum += __shfl_down_sync(0xffffffffu, sum, off);
    if ((tid & 31) == 0) warp_sums[tid >> 5] = sum;
    __syncthreads();
    float S_local = 0.0f;
    #pragma unroll
    for (int w = 0; w < NWARP; w++) S_local += warp_sums[w];

    // ---- Cross-CTA exchange: push my half-sum into the peer's smem ----
    if (tid == 0) {
        const uint32_t laddr = smem_addr_u32(&peer_sum);
        const uint32_t prank = half ^ 1;
        asm volatile(
            "{ .reg .b32 r;\n\t"
            "mapa.shared::cluster.u32 r, %0, %1;\n\t"
            "st.shared::cluster.f32 [r], %2; }"
            :: "r"(laddr), "r"(prank), "f"(S_local) : "memory");
    }
    asm volatile("barrier.cluster.arrive.aligned;" ::: "memory");
    asm volatile("barrier.cluster.wait.aligned;"   ::: "memory");

    const float S = S_local + peer_sum;
    const float s = ALPHA / (1.0f + S - 2.0f * t);
    const float corr = 1.0f - s * S;

    // Label ownership within this half (local float4 index).
    const int li   = lab - half * HALF_F;    // may be out of [0,HALF_F)
    const int lab4 = li >> 2;                // compared against local i
    const int labc = li & 3;

    // ---- Phase 2: re-read from pinned L2, REVERSED (hottest first) ----
    #pragma unroll
    for (int k = P2ITER - 1; k >= 0; k--) {
        const int i = tid + k * THREADS;
        if (k < P2ITER - 1 || i < H4) {
            const float4 w = __ldcs(&xh4[i]);
            float4 o;
            o.x = s * w.x;
            o.y = s * w.y;
            o.z = s * w.z;
            o.w = s * w.w;
            if (i == lab4) reinterpret_cast<float*>(&o)[labc] += corr;
            oh4[i] = o;
        }
    }
}

extern "C" void kernel_launch(void* const* d_in, const int* in_sizes, int n_in,
                              void* d_out, int out_size) {
    const float* teacher_logits = (const float*)d_in[0];
    const void*  true_labels    = d_in[1];
    float* out = (float*)d_out;

    const int batch = in_sizes[1];   // 4096 rows

    distill_kernel<<<2 * batch, THREADS>>>(teacher_logits, true_labels, out);
}